// round 3
// baseline (speedup 1.0000x reference)
#include <cuda_runtime.h>

// ProductVectorQuantizer: B=64,T=2048,D=512, C=4,K=128,d=128
// out (float32) = [quantized (N*512), encoding_indices (N), loss (N)]

#define CB    4
#define KC    128
#define ROWS  128
#define NTHR  512
#define JC4   32      // float4 chunks per 128-float segment
#define EKP   129     // k-stride (in float4) of transposed E tile: E_s[jc][k]
#define XPAD  33      // float4 stride per x row

__device__ __forceinline__ void ffma2(unsigned long long &a,
                                      unsigned long long x,
                                      unsigned long long e) {
    asm("fma.rn.f32x2 %0, %1, %2, %0;" : "+l"(a) : "l"(x), "l"(e));
}

extern __shared__ float4 smem4[];

__global__ __launch_bounds__(NTHR)
void pvq_kernel(const float* __restrict__ gin, const float* __restrict__ gemb,
                float* __restrict__ gout, int Nrows)
{
    float4* E_s = smem4;                           // [32][129] float4 : E_s[jc*EKP + k]
    float4* x_s = E_s + JC4 * EKP;                 // [128][33] float4 : x_s[row*XPAD + jc]
    float*  e2_s   = (float*)(x_s + ROWS * XPAD);  // [128]
    float*  loss_s = e2_s + KC;                    // [128]
    int*    pack_s = (int*)(loss_s + ROWS);        // [128]
    int*    idx_s  = pack_s + ROWS;                // [128]

    const int t    = threadIdx.x;
    const int kg   = t & 15;      // 16 code groups; thread covers codes k = i*16+kg
    const int rg   = t >> 4;      // 32 row groups; thread covers rows rg*4 .. rg*4+3
    const int n0   = blockIdx.x * ROWS;
    const int wid  = t >> 5;
    const int lane = t & 31;

    if (t < ROWS) { loss_s[t] = 0.0f; pack_s[t] = 0; }

    for (int c = 0; c < CB; ++c) {
        __syncthreads();   // previous phase fully consumed before overwrite

        // ---- stage codebook c (transposed): gmem [k][jc] coalesced -> E_s[jc][k] ----
        const float4* gE = (const float4*)(gemb + (size_t)c * KC * 128);
        #pragma unroll
        for (int idx = t; idx < KC * JC4; idx += NTHR) {
            int k = idx >> 5, jc = idx & 31;       // warp: k fixed, jc 0..31 -> 4-phase STS
            E_s[jc * EKP + k] = gE[idx];
        }
        // ---- stage x tile: 128 rows, segment c ----
        const float4* gx = (const float4*)gin;
        #pragma unroll
        for (int idx = t; idx < ROWS * JC4; idx += NTHR) {
            int row = idx >> 5, jc = idx & 31;
            x_s[row * XPAD + jc] = gx[(size_t)(n0 + row) * 128 + c * 32 + jc];
        }
        __syncthreads();

        // ---- e2[k] = ||E_k||^2 ----
        if (t < KC) {
            float s = 0.0f;
            #pragma unroll
            for (int jc = 0; jc < JC4; ++jc) {
                float4 e = E_s[jc * EKP + t];
                s += e.x * e.x + e.y * e.y + e.z * e.z + e.w * e.w;
            }
            e2_s[t] = s;
        }
        __syncthreads();

        // ---- dots: thread computes 4 rows x 8 codes, f32x2-packed over j ----
        unsigned long long acc[4][8];
        #pragma unroll
        for (int rr = 0; rr < 4; ++rr)
            #pragma unroll
            for (int i = 0; i < 8; ++i) acc[rr][i] = 0ULL;

        const ulonglong2* Ev = (const ulonglong2*)E_s;
        const ulonglong2* Xv = (const ulonglong2*)x_s;

        #pragma unroll 2
        for (int jc = 0; jc < JC4; ++jc) {
            unsigned long long xa[4][2];
            #pragma unroll
            for (int rr = 0; rr < 4; ++rr) {       // 2 distinct addrs/warp: broadcast, 1 phase
                ulonglong2 v = Xv[(rg * 4 + rr) * XPAD + jc];
                xa[rr][0] = v.x; xa[rr][1] = v.y;
            }
            #pragma unroll
            for (int i = 0; i < 8; ++i) {          // 16 contiguous float4, bcast x2: 2 phases
                ulonglong2 ev = Ev[jc * EKP + (i * 16 + kg)];
                #pragma unroll
                for (int rr = 0; rr < 4; ++rr) {
                    ffma2(acc[rr][i], xa[rr][0], ev.x);
                    ffma2(acc[rr][i], xa[rr][1], ev.y);
                }
            }
        }

        // ---- argmin per row (x2 const per row -> compare e2 - 2*dot; tie -> min k) ----
        #pragma unroll
        for (int rr = 0; rr < 4; ++rr) {
            float best = 3.0e38f; int bk = KC;
            #pragma unroll
            for (int i = 0; i < 8; ++i) {
                int k = i * 16 + kg;
                float lo, hi;
                asm("mov.b64 {%0,%1}, %2;" : "=f"(lo), "=f"(hi) : "l"(acc[rr][i]));
                float score = e2_s[k] - 2.0f * (lo + hi);
                if (score < best || (score == best && k < bk)) { best = score; bk = k; }
            }
            #pragma unroll
            for (int off = 8; off > 0; off >>= 1) {   // reduce across the 16 kg lanes
                float v2 = __shfl_xor_sync(0xffffffffu, best, off);
                int   k2 = __shfl_xor_sync(0xffffffffu, bk,   off);
                if (v2 < best || (v2 == best && k2 < bk)) { best = v2; bk = k2; }
            }
            if (kg == 0) idx_s[rg * 4 + rr] = bk;
        }
        __syncthreads();

        // ---- gather quantized, write out, exact loss ||q-x||^2 accumulation ----
        const int shift = 21 - 7 * c;                 // K^(3-c) as a shift (K=128)
        #pragma unroll
        for (int it = 0; it < 8; ++it) {
            int row = it * 16 + wid;                  // one warp per row, 16 warps
            int k   = idx_s[row];
            float4 e  = E_s[lane * EKP + k];          // 4-phase (min for 512B)
            float4 xv = x_s[row * XPAD + lane];       // 4-phase
            ((float4*)gout)[(size_t)(n0 + row) * 128 + c * 32 + lane] = e;
            float dx = e.x - xv.x, dy = e.y - xv.y, dz = e.z - xv.z, dw = e.w - xv.w;
            float s = dx * dx + dy * dy + dz * dz + dw * dw;
            #pragma unroll
            for (int off = 16; off > 0; off >>= 1)
                s += __shfl_xor_sync(0xffffffffu, s, off);
            if (lane == 0) {
                loss_s[row] += s;
                pack_s[row] += k << shift;
            }
        }
    }

    __syncthreads();
    if (t < ROWS) {
        size_t n = (size_t)n0 + t;
        float* idx_out  = gout + (size_t)Nrows * 512;
        float* loss_out = idx_out + Nrows;
        idx_out[n]  = (float)pack_s[t];
        loss_out[n] = 1.25f * loss_s[t];   // q_latent + COMMITMENT_COST*e_latent
    }
}

extern "C" void kernel_launch(void* const* d_in, const int* in_sizes, int n_in,
                              void* d_out, int out_size)
{
    const float* gin  = (const float*)d_in[0];   // inputs (B,T,D) f32
    const float* gemb = (const float*)d_in[1];   // embeddings (C,K,d) f32
    int Nrows = in_sizes[0] / 512;               // 131072

    int smem = (JC4 * EKP + ROWS * XPAD) * 16           // E_s + x_s
             + KC * 4 + ROWS * 4 + ROWS * 4 + ROWS * 4; // e2 + loss + pack + idx
    cudaFuncSetAttribute(pvq_kernel, cudaFuncAttributeMaxDynamicSharedMemorySize, smem);
    pvq_kernel<<<Nrows / ROWS, NTHR, smem>>>(gin, gemb, (float*)d_out, Nrows);
}

// round 6
// speedup vs baseline: 1.1139x; 1.1139x over previous
#include <cuda_runtime.h>

// ProductVectorQuantizer: B=64,T=2048,D=512, C=4,K=128,d=128
// out (float32) = [quantized (N*512), encoding_indices (N), loss (N)]

#define CB    4
#define KC    128
#define ROWS  64
#define NTHR  256
#define JC4   32      // float4 chunks per 128-float segment
#define EKP   129     // k-stride (in float4) of transposed E tile: E_s[jc][k]
#define XPAD  33      // float4 stride per x row

__device__ float e2g[CB * KC];   // ||E_ck||^2, filled by prologue kernel

__global__ void e2_kernel(const float* __restrict__ gemb) {
    int c = blockIdx.x, k = threadIdx.x;           // 4 blocks x 128 threads
    const float4* row = (const float4*)(gemb + ((size_t)c * KC + k) * 128);
    float s = 0.0f;
    #pragma unroll
    for (int jc = 0; jc < JC4; ++jc) {
        float4 e = row[jc];
        s += e.x * e.x + e.y * e.y + e.z * e.z + e.w * e.w;
    }
    e2g[c * KC + k] = s;
}

__device__ __forceinline__ void ffma2(unsigned long long &a,
                                      unsigned long long x,
                                      unsigned long long e) {
    asm("fma.rn.f32x2 %0, %1, %2, %0;" : "+l"(a) : "l"(x), "l"(e));
}

extern __shared__ float4 smem4[];

__global__ __launch_bounds__(NTHR, 2)
void pvq_kernel(const float* __restrict__ gin, const float* __restrict__ gemb,
                float* __restrict__ gout, int Nrows)
{
    float4* E_s = smem4;                           // [32][129] float4 : E_s[jc*EKP + k]
    float4* x_s = E_s + JC4 * EKP;                 // [64][33]  float4 : x_s[row*XPAD + jc]
    float*  e2_s = (float*)(x_s + ROWS * XPAD);    // [128]

    const int t    = threadIdx.x;
    const int kg   = t & 15;        // code group: thread covers codes k = i*16+kg
    const int rg   = t >> 4;        // row group:  thread covers rows rg*4 .. rg*4+3
    const int n0   = blockIdx.x * ROWS;
    const int w    = t >> 5;        // warp id: warp w owns rows 8w..8w+7 end-to-end
    const int lane = t & 31;

    float loss8[8];
    int   pack8[8];
    #pragma unroll
    for (int i = 0; i < 8; ++i) { loss8[i] = 0.0f; pack8[i] = 0; }

    for (int c = 0; c < CB; ++c) {
        __syncthreads();   // previous phase fully consumed before overwrite

        // ---- stage codebook c (transposed): gmem [k][jc] -> E_s[jc][k] ----
        const float4* gE = (const float4*)(gemb + (size_t)c * KC * 128);
        #pragma unroll
        for (int it = 0; it < (KC * JC4) / NTHR; ++it) {
            int idx = it * NTHR + t;
            int k = idx >> 5, jc = idx & 31;
            E_s[jc * EKP + k] = gE[idx];
        }
        // ---- stage x tile: 64 rows, segment c ----
        const float4* gx = (const float4*)gin;
        #pragma unroll
        for (int it = 0; it < (ROWS * JC4) / NTHR; ++it) {
            int idx = it * NTHR + t;
            int row = idx >> 5, jc = idx & 31;
            x_s[row * XPAD + jc] = gx[(size_t)(n0 + row) * 128 + c * 32 + jc];
        }
        if (t < KC) e2_s[t] = e2g[c * KC + t];     // precomputed norms
        __syncthreads();

        // ---- dots: thread computes 4 rows x 8 codes, f32x2-packed over j ----
        unsigned long long acc[4][8];
        #pragma unroll
        for (int rr = 0; rr < 4; ++rr)
            #pragma unroll
            for (int i = 0; i < 8; ++i) acc[rr][i] = 0ULL;

        const ulonglong2* Ev = (const ulonglong2*)E_s;
        const ulonglong2* Xv = (const ulonglong2*)x_s;

        #pragma unroll 4
        for (int jc = 0; jc < JC4; ++jc) {
            unsigned long long xa[4][2];
            #pragma unroll
            for (int rr = 0; rr < 4; ++rr) {       // 2 distinct addrs/warp: broadcast
                ulonglong2 v = Xv[(rg * 4 + rr) * XPAD + jc];
                xa[rr][0] = v.x; xa[rr][1] = v.y;
            }
            #pragma unroll
            for (int i = 0; i < 8; ++i) {          // 16 contiguous float4 x2 halves
                ulonglong2 ev = Ev[jc * EKP + (i * 16 + kg)];
                #pragma unroll
                for (int rr = 0; rr < 4; ++rr) {
                    ffma2(acc[rr][i], xa[rr][0], ev.x);
                    ffma2(acc[rr][i], xa[rr][1], ev.y);
                }
            }
        }

        // ---- argmin per row (compare e2 - 2*dot; tie -> min k) ----
        int bk[4];
        #pragma unroll
        for (int rr = 0; rr < 4; ++rr) {
            float best = 3.0e38f; int b = KC;
            #pragma unroll
            for (int i = 0; i < 8; ++i) {
                int k = i * 16 + kg;
                float lo, hi;
                asm("mov.b64 {%0,%1}, %2;" : "=f"(lo), "=f"(hi) : "l"(acc[rr][i]));
                float score = e2_s[k] - 2.0f * (lo + hi);
                if (score < best || (score == best && k < b)) { best = score; b = k; }
            }
            #pragma unroll
            for (int off = 8; off > 0; off >>= 1) {   // reduce across 16 kg lanes (in-half)
                float v2 = __shfl_xor_sync(0xffffffffu, best, off);
                int   k2 = __shfl_xor_sync(0xffffffffu, b,    off);
                if (v2 < best || (v2 == best && k2 < b)) { best = v2; b = k2; }
            }
            bk[rr] = b;   // uniform within each 16-lane half
        }

        // ---- epilogue (no sync needed: warp w owns rows 8w..8w+7) ----
        const int shift = 21 - 7 * c;                 // K^(3-c) as shift (K=128)
        #pragma unroll
        for (int h = 0; h < 2; ++h) {
            #pragma unroll
            for (int rr = 0; rr < 4; ++rr) {
                int row = 8 * w + 4 * h + rr;
                int k   = __shfl_sync(0xffffffffu, bk[rr], h * 16);
                float4 e  = E_s[lane * EKP + k];
                float4 xv = x_s[row * XPAD + lane];
                ((float4*)gout)[(size_t)(n0 + row) * 128 + c * 32 + lane] = e;
                float dx = e.x - xv.x, dy = e.y - xv.y,
                      dz = e.z - xv.z, dw = e.w - xv.w;
                float s = dx * dx + dy * dy + dz * dz + dw * dw;
                #pragma unroll
                for (int off = 16; off > 0; off >>= 1)
                    s += __shfl_xor_sync(0xffffffffu, s, off);
                int it = 4 * h + rr;
                loss8[it] += s;
                pack8[it] += k << shift;
            }
        }
    }

    // ---- final per-row scalar outputs (warp-owned rows) ----
    float* idx_out  = gout + (size_t)Nrows * 512;
    float* loss_out = idx_out + Nrows;
    #pragma unroll
    for (int it = 0; it < 8; ++it) {
        if (lane == it) {
            size_t n = (size_t)n0 + 8 * w + it;
            idx_out[n]  = (float)pack8[it];
            loss_out[n] = 1.25f * loss8[it];   // q_latent + COMMITMENT_COST*e_latent
        }
    }
}

extern "C" void kernel_launch(void* const* d_in, const int* in_sizes, int n_in,
                              void* d_out, int out_size)
{
    const float* gin  = (const float*)d_in[0];   // inputs (B,T,D) f32
    const float* gemb = (const float*)d_in[1];   // embeddings (C,K,d) f32
    int Nrows = in_sizes[0] / 512;               // 131072

    int smem = (JC4 * EKP + ROWS * XPAD) * 16 + KC * 4;   // E_s + x_s + e2_s
    cudaFuncSetAttribute(pvq_kernel, cudaFuncAttributeMaxDynamicSharedMemorySize, smem);

    e2_kernel<<<CB, KC>>>(gemb);
    pvq_kernel<<<Nrows / ROWS, NTHR, smem>>>(gin, gemb, (float*)d_out, Nrows);
}